// round 13
// baseline (speedup 1.0000x reference)
#include <cuda_runtime.h>
#include <cuda_fp16.h>
#include <math.h>

#define N_NODES 100000
#define E_EDGES 3200000
#define F_IN    500
#define HID     64
#define CCH     64
#define KFREQ   5
#define DORD    10

// ---------------- scratch (static device globals; no allocation) ----------------
__device__ __align__(16) float  g_xh[N_NODES * HID];     // relu(feature@W1+b1)
__device__ __align__(16) float  g_xc[N_NODES * CCH];     // lin2 output fp32
__device__ __align__(16) __half g_u0[N_NODES * CCH];     // u0 = dinv*xc (fp16)
__device__ __align__(16) __half g_uA[N_NODES * CCH];     // fp16 scaled-state ping (odd d)
__device__ __align__(16) __half g_uB[N_NODES * CCH];     // fp16 scaled-state pong (even d)
__device__ __align__(16) float  g_hidden[N_NODES * CCH]; // fp32 accumulator (init c0*xc)
__device__ int    g_src[E_EDGES];                        // CSR-by-dst: src per edge
__device__ int    g_deg[N_NODES];
__device__ int    g_indeg[N_NODES];
__device__ float  g_dinv[N_NODES];
__device__ int    g_rowptr[N_NODES + 1];
__device__ int    g_cursor[N_NODES + 1];
__device__ int    g_tmp[N_NODES];
__device__ int    g_btot[128];
__device__ int    g_boff[128];
__device__ float  g_coeff[16];

// ---------------- small utility kernels ----------------
__global__ void zero_counts_kernel() {
    int i = blockIdx.x * blockDim.x + threadIdx.x;
    if (i < N_NODES) { g_deg[i] = 0; g_indeg[i] = 0; }
}

// coeff[d] = sum_k alpha[k]*SINC[k][d] + beta[k]*COSC[k][d] (tables in fp64, cast)
__global__ void coeff_kernel(const float* __restrict__ alpha,
                             const float* __restrict__ beta) {
    int d = threadIdx.x;
    if (d > DORD) return;
    float acc = 0.0f;
    for (int k = 0; k < KFREQ; ++k) {
        double x = (double)(k + 1) * 3.14159265358979323846;
        double p = 1.0;
        for (int i = 0; i < d; ++i) p *= x;
        double f = 1.0;
        for (int i = 2; i <= d; ++i) f *= (double)i;
        double sinc = 0.0, cosc = 0.0;
        if ((d & 1) == 0) {
            double sgn = (((d / 2) & 1) == 0) ? 1.0 : -1.0;
            cosc = sgn * p / f;
        } else {
            double sgn = ((((d - 1) / 2) & 1) == 0) ? 1.0 : -1.0;
            sinc = sgn * p / f;
        }
        acc += alpha[k] * (float)sinc + beta[k] * (float)cosc;
    }
    g_coeff[d] = acc;
}

// edges buffer is int32 (jax x64 disabled)
__global__ void pass1_kernel(const int* __restrict__ edges) {
    int e = blockIdx.x * blockDim.x + threadIdx.x;
    if (e >= E_EDGES) return;
    int s = edges[e];
    int d = edges[E_EDGES + e];
    if (s != d && (unsigned)s < N_NODES && (unsigned)d < N_NODES) {
        atomicAdd(&g_deg[s], 1);
        atomicAdd(&g_indeg[d], 1);
    }
}

__global__ void dinv_kernel() {
    int i = blockIdx.x * blockDim.x + threadIdx.x;
    if (i >= N_NODES) return;
    int dg = g_deg[i];
    g_dinv[i] = (dg > 0) ? rsqrtf((float)dg) : 0.0f;
}

// ------- exclusive scan of g_indeg -> g_rowptr -------
__global__ void scan1_kernel(int n) {
    __shared__ int s[1024];
    int i = blockIdx.x * 1024 + threadIdx.x;
    int v = (i < n) ? g_indeg[i] : 0;
    s[threadIdx.x] = v;
    __syncthreads();
    for (int off = 1; off < 1024; off <<= 1) {
        int t = (threadIdx.x >= off) ? s[threadIdx.x - off] : 0;
        __syncthreads();
        s[threadIdx.x] += t;
        __syncthreads();
    }
    if (i < n) g_tmp[i] = s[threadIdx.x];
    if (threadIdx.x == 1023) g_btot[blockIdx.x] = s[1023];
}

__global__ void scan2_kernel(int nb) {
    if (threadIdx.x == 0 && blockIdx.x == 0) {
        int run = 0;
        for (int b = 0; b < nb; ++b) { g_boff[b] = run; run += g_btot[b]; }
    }
}

__global__ void scan3_kernel(int n) {
    int i = blockIdx.x * 1024 + threadIdx.x;
    if (i < n) {
        int v = g_tmp[i] + g_boff[blockIdx.x];
        g_rowptr[i + 1] = v;
        if (i + 1 < N_NODES) g_cursor[i + 1] = v;
        if (i == 0) { g_rowptr[0] = 0; g_cursor[0] = 0; }
    }
}

__global__ void scatter_kernel(const int* __restrict__ edges) {
    int e = blockIdx.x * blockDim.x + threadIdx.x;
    if (e >= E_EDGES) return;
    int s = edges[e];
    int d = edges[E_EDGES + e];
    if (s != d && (unsigned)s < N_NODES && (unsigned)d < N_NODES) {
        int pos = atomicAdd(&g_cursor[d], 1);
        g_src[pos] = s;
    }
}

// ---------------- packed f32x2 FMA helper ----------------
__device__ __forceinline__ void ffma2(unsigned long long& acc,
                                      unsigned long long a,
                                      unsigned long long b) {
    asm("fma.rn.f32x2 %0, %1, %2, %0;" : "+l"(acc) : "l"(a), "l"(b));
}
__device__ __forceinline__ float2 unpack2(unsigned long long p) {
    float2 r;
    asm("mov.b64 {%0, %1}, %2;" : "=f"(r.x), "=f"(r.y) : "l"(p));
    return r;
}

// ---------------- GEMM1: xh = relu(feature @ W1 + b1) ----------------
__global__ __launch_bounds__(256) void gemm1_kernel(const float* __restrict__ feat,
                                                    const float* __restrict__ W1,
                                                    const float* __restrict__ b1) {
    __shared__ __align__(16) float2 As2[16 * 65];
    __shared__ __align__(16) float  Ws[16 * 64];
    int tid = threadIdx.x;
    int tx = tid & 15, ty = tid >> 4;
    int row0 = blockIdx.x * 64;
    int kkA = tid & 15;
    int rA = (tid >> 4) * 4;
    unsigned long long acc[4][2] = {};

    for (int k0 = 0; k0 < F_IN; k0 += 16) {
        bool kok = (k0 + kkA) < F_IN;
#pragma unroll
        for (int i = 0; i < 4; ++i) {
            int r = row0 + rA + i;
            float v = 0.0f;
            if (r < N_NODES && kok) v = __ldcs(&feat[r * F_IN + k0 + kkA]);
            As2[kkA * 65 + rA + i] = make_float2(v, v);
        }
        {
            int L = tid * 4;
            int kk = L >> 6;
            int n = L & 63;
            float4 w4 = make_float4(0.f, 0.f, 0.f, 0.f);
            if (k0 + kk < F_IN) w4 = *(const float4*)&W1[(k0 + kk) * HID + n];
            *(float4*)&Ws[kk * 64 + n] = w4;
        }
        __syncthreads();
#pragma unroll
        for (int kk = 0; kk < 16; ++kk) {
            ulonglong2 bp = *(const ulonglong2*)&Ws[kk * 64 + tx * 4];
            const unsigned long long* ap =
                (const unsigned long long*)&As2[kk * 65 + ty * 4];
#pragma unroll
            for (int i = 0; i < 4; ++i) {
                unsigned long long a = ap[i];
                ffma2(acc[i][0], a, bp.x);
                ffma2(acc[i][1], a, bp.y);
            }
        }
        __syncthreads();
    }
#pragma unroll
    for (int i = 0; i < 4; ++i) {
        int r = row0 + ty * 4 + i;
        if (r >= N_NODES) continue;
        float2 p0 = unpack2(acc[i][0]);
        float2 p1 = unpack2(acc[i][1]);
        int c = tx * 4;
        g_xh[r * HID + c + 0] = fmaxf(p0.x + __ldg(&b1[c + 0]), 0.0f);
        g_xh[r * HID + c + 1] = fmaxf(p0.y + __ldg(&b1[c + 1]), 0.0f);
        g_xh[r * HID + c + 2] = fmaxf(p1.x + __ldg(&b1[c + 2]), 0.0f);
        g_xh[r * HID + c + 3] = fmaxf(p1.y + __ldg(&b1[c + 3]), 0.0f);
    }
}

// ---------------- GEMM2: xc = xh @ W2 + b2 ; hidden = c0*xc ; u0 = dinv*xc ----------------
__global__ __launch_bounds__(256) void gemm2_kernel(const float* __restrict__ W2,
                                                    const float* __restrict__ b2) {
    __shared__ __align__(16) float2 As2[16 * 65];
    __shared__ __align__(16) float  Ws[16 * 64];
    int tid = threadIdx.x;
    int tx = tid & 15, ty = tid >> 4;
    int row0 = blockIdx.x * 64;
    int kkA = tid & 15;
    int rA = (tid >> 4) * 4;
    unsigned long long acc[4][2] = {};

    for (int k0 = 0; k0 < HID; k0 += 16) {
#pragma unroll
        for (int i = 0; i < 4; ++i) {
            int r = row0 + rA + i;
            float v = 0.0f;
            if (r < N_NODES) v = g_xh[r * HID + k0 + kkA];
            As2[kkA * 65 + rA + i] = make_float2(v, v);
        }
        {
            int L = tid * 4;
            int kk = L >> 6;
            int n = L & 63;
            float4 w4 = *(const float4*)&W2[(k0 + kk) * CCH + n];
            *(float4*)&Ws[kk * 64 + n] = w4;
        }
        __syncthreads();
#pragma unroll
        for (int kk = 0; kk < 16; ++kk) {
            ulonglong2 bp = *(const ulonglong2*)&Ws[kk * 64 + tx * 4];
            const unsigned long long* ap =
                (const unsigned long long*)&As2[kk * 65 + ty * 4];
#pragma unroll
            for (int i = 0; i < 4; ++i) {
                unsigned long long a = ap[i];
                ffma2(acc[i][0], a, bp.x);
                ffma2(acc[i][1], a, bp.y);
            }
        }
        __syncthreads();
    }
    float c0 = g_coeff[0];
#pragma unroll
    for (int i = 0; i < 4; ++i) {
        int r = row0 + ty * 4 + i;
        if (r >= N_NODES) continue;
        float2 p0 = unpack2(acc[i][0]);
        float2 p1 = unpack2(acc[i][1]);
        int c = tx * 4;
        float v0 = p0.x + __ldg(&b2[c + 0]);
        float v1 = p0.y + __ldg(&b2[c + 1]);
        float v2 = p1.x + __ldg(&b2[c + 2]);
        float v3 = p1.y + __ldg(&b2[c + 3]);
        float* xr = &g_xc[r * CCH + c];
        xr[0] = v0; xr[1] = v1; xr[2] = v2; xr[3] = v3;
        float* hr = &g_hidden[r * CCH + c];
        hr[0] = c0 * v0; hr[1] = c0 * v1; hr[2] = c0 * v2; hr[3] = c0 * v3;
        float di = __ldg(&g_dinv[r]);       // u0 = dinv * xc
        __half2* u0 = (__half2*)&g_u0[r * CCH + c];
        u0[0] = __floats2half2_rn(di * v0, di * v1);
        u0[1] = __floats2half2_rn(di * v2, di * v3);
    }
}

// ---------------- hop gather: sum of u over the row's sources ----------------
// Warp loads 32 src ids coalesced, shfl-broadcasts, then 32 independent 128B
// row gathers (pure sum, no per-edge weight — factorized into dinv).
__device__ __forceinline__ float2 row_gather(const __half2* __restrict__ tin,
                                             int beg, int end, int lane) {
    float2 acc = make_float2(0.f, 0.f);
    const __half2* tlane = tin + lane;
    int j0 = beg;
    for (; j0 + 32 <= end; j0 += 32) {
        int s = __ldg(&g_src[j0 + lane]);
#pragma unroll
        for (int t = 0; t < 32; ++t) {
            int ss = __shfl_sync(0xFFFFFFFFu, s, t);
            float2 v = __half22float2(__ldg(&tlane[ss * 32]));
            acc.x += v.x; acc.y += v.y;
        }
    }
    int n = end - j0;
    if (n > 0) {
        int s = (lane < n) ? __ldg(&g_src[j0 + lane]) : 0;
#pragma unroll 8
        for (int t = 0; t < n; ++t) {
            int ss = __shfl_sync(0xFFFFFFFFu, s, t);
            float2 v = __half22float2(__ldg(&tlane[ss * 32]));
            acc.x += v.x; acc.y += v.y;
        }
    }
    return acc;
}

// hop d: Tx = -dinv * sum(u_{d-1}[src]) (fp32, unrounded -> hidden);
//        u_d = dinv * Tx (fp16, next gather). d odd -> writes A, even -> B.
// hidden RMW uses in-register fp32 Tx: the alternating-sign coeff sum must NOT
// see fp16-rounded terms (R12 lesson).
__global__ __launch_bounds__(512) void hop_kernel(int d) {
    int row = blockIdx.x * 16 + (threadIdx.x >> 5);
    if (row >= N_NODES) return;
    int lane = threadIdx.x & 31;

    const __half2* tin = (d == 1) ? (const __half2*)g_u0
                        : ((d & 1) ? (const __half2*)g_uB : (const __half2*)g_uA);
    __half2* tout = (d & 1) ? (__half2*)g_uA : (__half2*)g_uB;

    int beg = __ldg(&g_rowptr[row]);
    int end = __ldg(&g_rowptr[row + 1]);
    float2 acc = row_gather(tin, beg, end, lane);
    float di = __ldg(&g_dinv[row]);
    float txx = -di * acc.x;
    float txy = -di * acc.y;
    int idx = row * 32 + lane;
    tout[idx] = __floats2half2_rn(di * txx, di * txy);
    float c = g_coeff[d];
    float2 h = __ldcs(&((float2*)g_hidden)[idx]);
    h.x = fmaf(c, txx, h.x);
    h.y = fmaf(c, txy, h.y);
    __stcs(&((float2*)g_hidden)[idx], h);
}

// ---------------- last hop (d=10) fused with log_softmax epilogue ----------------
// d=9 odd -> its output is in g_uA.
__global__ __launch_bounds__(512) void hop_final_kernel(float* __restrict__ out) {
    int row = blockIdx.x * 16 + (threadIdx.x >> 5);
    if (row >= N_NODES) return;
    int lane = threadIdx.x & 31;

    int beg = __ldg(&g_rowptr[row]);
    int end = __ldg(&g_rowptr[row + 1]);
    float2 acc = row_gather((const __half2*)g_uA, beg, end, lane);
    float di = __ldg(&g_dinv[row]);

    int idx = row * 32 + lane;
    float c = g_coeff[DORD];
    float2 h = __ldcs(&((const float2*)g_hidden)[idx]);
    float2 x = __ldcs(&((const float2*)g_xc)[idx]);
    float vx = fmaf(c, -di * acc.x, h.x) + x.x;
    float vy = fmaf(c, -di * acc.y, h.y) + x.y;
    float m = fmaxf(vx, vy);
#pragma unroll
    for (int o = 16; o; o >>= 1) m = fmaxf(m, __shfl_xor_sync(0xFFFFFFFFu, m, o));
    float s = expf(vx - m) + expf(vy - m);
#pragma unroll
    for (int o = 16; o; o >>= 1) s += __shfl_xor_sync(0xFFFFFFFFu, s, o);
    float l = m + logf(s);
    __stcs(&((float2*)out)[idx], make_float2(vx - l, vy - l));
}

// ---------------- launch ----------------
extern "C" void kernel_launch(void* const* d_in, const int* in_sizes, int n_in,
                              void* d_out, int out_size) {
    const float* feature = (const float*)d_in[0];
    const int*   edges   = (const int*)d_in[1];   // int32
    const float* W1      = (const float*)d_in[2];
    const float* b1      = (const float*)d_in[3];
    const float* W2      = (const float*)d_in[4];
    const float* b2      = (const float*)d_in[5];
    const float* alpha   = (const float*)d_in[6];
    const float* beta    = (const float*)d_in[7];
    float* out           = (float*)d_out;

    const int TB = 256;
    int gN   = (N_NODES + TB - 1) / TB;
    int gE   = (E_EDGES + TB - 1) / TB;
    int gRow = (N_NODES + 15) / 16;          // 512-thr warp-per-row kernels
    int gG   = (N_NODES + 63) / 64;
    int nb   = (N_NODES + 1023) / 1024;

    zero_counts_kernel<<<gN, TB>>>();
    coeff_kernel<<<1, 32>>>(alpha, beta);
    pass1_kernel<<<gE, TB>>>(edges);
    dinv_kernel<<<gN, TB>>>();
    scan1_kernel<<<nb, 1024>>>(N_NODES);
    scan2_kernel<<<1, 32>>>(nb);
    scan3_kernel<<<nb, 1024>>>(N_NODES);
    scatter_kernel<<<gE, TB>>>(edges);

    gemm1_kernel<<<gG, TB>>>(feature, W1, b1);
    gemm2_kernel<<<gG, TB>>>(W2, b2);

    for (int d = 1; d < DORD; ++d)
        hop_kernel<<<gRow, 512>>>(d);
    hop_final_kernel<<<gRow, 512>>>(out);
}

// round 14
// speedup vs baseline: 1.6004x; 1.6004x over previous
#include <cuda_runtime.h>
#include <cuda_fp16.h>
#include <math.h>

#define N_NODES 100000
#define E_EDGES 3200000
#define F_IN    500
#define HID     64
#define CCH     64
#define KFREQ   5
#define DORD    10

// ---------------- scratch (static device globals; no allocation) ----------------
__device__ __align__(16) float  g_xh[N_NODES * HID];     // relu(feature@W1+b1)
__device__ __align__(16) float  g_xc[N_NODES * CCH];     // lin2 output fp32
__device__ __align__(16) __half g_u0[N_NODES * CCH];     // u0 = dinv*xc (fp16)
__device__ __align__(16) __half g_uA[N_NODES * CCH];     // fp16 scaled-state ping (odd d)
__device__ __align__(16) __half g_uB[N_NODES * CCH];     // fp16 scaled-state pong (even d)
__device__ __align__(16) float  g_hidden[N_NODES * CCH]; // fp32 accumulator (init c0*xc)
__device__ int    g_src[E_EDGES];                        // CSR-by-dst: src per edge
__device__ int    g_deg[N_NODES];
__device__ int    g_indeg[N_NODES];
__device__ float  g_dinv[N_NODES];
__device__ int    g_rowptr[N_NODES + 1];
__device__ int    g_cursor[N_NODES + 1];
__device__ int    g_tmp[N_NODES];
__device__ int    g_btot[128];
__device__ int    g_boff[128];
__device__ float  g_coeff[16];

// ---------------- init: zero counters + Taylor coeffs (fused) ----------------
__global__ void init_kernel(const float* __restrict__ alpha,
                            const float* __restrict__ beta) {
    int i = blockIdx.x * blockDim.x + threadIdx.x;
    if (i < N_NODES) { g_deg[i] = 0; g_indeg[i] = 0; }
    if (blockIdx.x == 0 && threadIdx.x <= DORD) {
        int d = threadIdx.x;
        float acc = 0.0f;
        for (int k = 0; k < KFREQ; ++k) {
            double x = (double)(k + 1) * 3.14159265358979323846;
            double p = 1.0;
            for (int j = 0; j < d; ++j) p *= x;
            double f = 1.0;
            for (int j = 2; j <= d; ++j) f *= (double)j;
            double sinc = 0.0, cosc = 0.0;
            if ((d & 1) == 0) {
                double sgn = (((d / 2) & 1) == 0) ? 1.0 : -1.0;
                cosc = sgn * p / f;
            } else {
                double sgn = ((((d - 1) / 2) & 1) == 0) ? 1.0 : -1.0;
                sinc = sgn * p / f;
            }
            acc += alpha[k] * (float)sinc + beta[k] * (float)cosc;
        }
        g_coeff[d] = acc;
    }
}

// edges buffer is int32 (jax x64 disabled)
__global__ void pass1_kernel(const int* __restrict__ edges) {
    int e = blockIdx.x * blockDim.x + threadIdx.x;
    if (e >= E_EDGES) return;
    int s = edges[e];
    int d = edges[E_EDGES + e];
    if (s != d && (unsigned)s < N_NODES && (unsigned)d < N_NODES) {
        atomicAdd(&g_deg[s], 1);
        atomicAdd(&g_indeg[d], 1);
    }
}

// ------- scan1 (block-local inclusive scan of indeg) + dinv fused -------
__global__ void scan1_kernel(int n) {
    __shared__ int s[1024];
    int i = blockIdx.x * 1024 + threadIdx.x;
    // fused dinv (independent of the scan data)
    if (i < n) {
        int dg = g_deg[i];
        g_dinv[i] = (dg > 0) ? rsqrtf((float)dg) : 0.0f;
    }
    int v = (i < n) ? g_indeg[i] : 0;
    s[threadIdx.x] = v;
    __syncthreads();
    for (int off = 1; off < 1024; off <<= 1) {
        int t = (threadIdx.x >= off) ? s[threadIdx.x - off] : 0;
        __syncthreads();
        s[threadIdx.x] += t;
        __syncthreads();
    }
    if (i < n) g_tmp[i] = s[threadIdx.x];
    if (threadIdx.x == 1023) g_btot[blockIdx.x] = s[1023];
}

__global__ void scan2_kernel(int nb) {
    if (threadIdx.x == 0 && blockIdx.x == 0) {
        int run = 0;
        for (int b = 0; b < nb; ++b) { g_boff[b] = run; run += g_btot[b]; }
    }
}

__global__ void scan3_kernel(int n) {
    int i = blockIdx.x * 1024 + threadIdx.x;
    if (i < n) {
        int v = g_tmp[i] + g_boff[blockIdx.x];
        g_rowptr[i + 1] = v;
        if (i + 1 < N_NODES) g_cursor[i + 1] = v;
        if (i == 0) { g_rowptr[0] = 0; g_cursor[0] = 0; }
    }
}

__global__ void scatter_kernel(const int* __restrict__ edges) {
    int e = blockIdx.x * blockDim.x + threadIdx.x;
    if (e >= E_EDGES) return;
    int s = edges[e];
    int d = edges[E_EDGES + e];
    if (s != d && (unsigned)s < N_NODES && (unsigned)d < N_NODES) {
        int pos = atomicAdd(&g_cursor[d], 1);
        g_src[pos] = s;
    }
}

// ---------------- packed f32x2 FMA helper ----------------
__device__ __forceinline__ void ffma2(unsigned long long& acc,
                                      unsigned long long a,
                                      unsigned long long b) {
    asm("fma.rn.f32x2 %0, %1, %2, %0;" : "+l"(acc) : "l"(a), "l"(b));
}
__device__ __forceinline__ float2 unpack2(unsigned long long p) {
    float2 r;
    asm("mov.b64 {%0, %1}, %2;" : "=f"(r.x), "=f"(r.y) : "l"(p));
    return r;
}

// ---------------- GEMM1: xh = relu(feature @ W1 + b1) ----------------
__global__ __launch_bounds__(256) void gemm1_kernel(const float* __restrict__ feat,
                                                    const float* __restrict__ W1,
                                                    const float* __restrict__ b1) {
    __shared__ __align__(16) float2 As2[16 * 65];
    __shared__ __align__(16) float  Ws[16 * 64];
    int tid = threadIdx.x;
    int tx = tid & 15, ty = tid >> 4;
    int row0 = blockIdx.x * 64;
    int kkA = tid & 15;
    int rA = (tid >> 4) * 4;
    unsigned long long acc[4][2] = {};

    for (int k0 = 0; k0 < F_IN; k0 += 16) {
        bool kok = (k0 + kkA) < F_IN;
#pragma unroll
        for (int i = 0; i < 4; ++i) {
            int r = row0 + rA + i;
            float v = 0.0f;
            if (r < N_NODES && kok) v = __ldcs(&feat[r * F_IN + k0 + kkA]);
            As2[kkA * 65 + rA + i] = make_float2(v, v);
        }
        {
            int L = tid * 4;
            int kk = L >> 6;
            int n = L & 63;
            float4 w4 = make_float4(0.f, 0.f, 0.f, 0.f);
            if (k0 + kk < F_IN) w4 = *(const float4*)&W1[(k0 + kk) * HID + n];
            *(float4*)&Ws[kk * 64 + n] = w4;
        }
        __syncthreads();
#pragma unroll
        for (int kk = 0; kk < 16; ++kk) {
            ulonglong2 bp = *(const ulonglong2*)&Ws[kk * 64 + tx * 4];
            const unsigned long long* ap =
                (const unsigned long long*)&As2[kk * 65 + ty * 4];
#pragma unroll
            for (int i = 0; i < 4; ++i) {
                unsigned long long a = ap[i];
                ffma2(acc[i][0], a, bp.x);
                ffma2(acc[i][1], a, bp.y);
            }
        }
        __syncthreads();
    }
#pragma unroll
    for (int i = 0; i < 4; ++i) {
        int r = row0 + ty * 4 + i;
        if (r >= N_NODES) continue;
        float2 p0 = unpack2(acc[i][0]);
        float2 p1 = unpack2(acc[i][1]);
        int c = tx * 4;
        g_xh[r * HID + c + 0] = fmaxf(p0.x + __ldg(&b1[c + 0]), 0.0f);
        g_xh[r * HID + c + 1] = fmaxf(p0.y + __ldg(&b1[c + 1]), 0.0f);
        g_xh[r * HID + c + 2] = fmaxf(p1.x + __ldg(&b1[c + 2]), 0.0f);
        g_xh[r * HID + c + 3] = fmaxf(p1.y + __ldg(&b1[c + 3]), 0.0f);
    }
}

// ---------------- GEMM2: xc = xh @ W2 + b2 ; hidden = c0*xc ; u0 = dinv*xc ----------------
__global__ __launch_bounds__(256) void gemm2_kernel(const float* __restrict__ W2,
                                                    const float* __restrict__ b2) {
    __shared__ __align__(16) float2 As2[16 * 65];
    __shared__ __align__(16) float  Ws[16 * 64];
    int tid = threadIdx.x;
    int tx = tid & 15, ty = tid >> 4;
    int row0 = blockIdx.x * 64;
    int kkA = tid & 15;
    int rA = (tid >> 4) * 4;
    unsigned long long acc[4][2] = {};

    for (int k0 = 0; k0 < HID; k0 += 16) {
#pragma unroll
        for (int i = 0; i < 4; ++i) {
            int r = row0 + rA + i;
            float v = 0.0f;
            if (r < N_NODES) v = g_xh[r * HID + k0 + kkA];
            As2[kkA * 65 + rA + i] = make_float2(v, v);
        }
        {
            int L = tid * 4;
            int kk = L >> 6;
            int n = L & 63;
            float4 w4 = *(const float4*)&W2[(k0 + kk) * CCH + n];
            *(float4*)&Ws[kk * 64 + n] = w4;
        }
        __syncthreads();
#pragma unroll
        for (int kk = 0; kk < 16; ++kk) {
            ulonglong2 bp = *(const ulonglong2*)&Ws[kk * 64 + tx * 4];
            const unsigned long long* ap =
                (const unsigned long long*)&As2[kk * 65 + ty * 4];
#pragma unroll
            for (int i = 0; i < 4; ++i) {
                unsigned long long a = ap[i];
                ffma2(acc[i][0], a, bp.x);
                ffma2(acc[i][1], a, bp.y);
            }
        }
        __syncthreads();
    }
    float c0 = g_coeff[0];
#pragma unroll
    for (int i = 0; i < 4; ++i) {
        int r = row0 + ty * 4 + i;
        if (r >= N_NODES) continue;
        float2 p0 = unpack2(acc[i][0]);
        float2 p1 = unpack2(acc[i][1]);
        int c = tx * 4;
        float v0 = p0.x + __ldg(&b2[c + 0]);
        float v1 = p0.y + __ldg(&b2[c + 1]);
        float v2 = p1.x + __ldg(&b2[c + 2]);
        float v3 = p1.y + __ldg(&b2[c + 3]);
        float* xr = &g_xc[r * CCH + c];
        xr[0] = v0; xr[1] = v1; xr[2] = v2; xr[3] = v3;
        float* hr = &g_hidden[r * CCH + c];
        hr[0] = c0 * v0; hr[1] = c0 * v1; hr[2] = c0 * v2; hr[3] = c0 * v3;
        float di = __ldg(&g_dinv[r]);       // u0 = dinv * xc
        __half2* u0 = (__half2*)&g_u0[r * CCH + c];
        u0[0] = __floats2half2_rn(di * v0, di * v1);
        u0[1] = __floats2half2_rn(di * v2, di * v3);
    }
}

// ---------------- hop gather: sum of u over the row's sources ----------------
// Warp loads 32 src ids coalesced, shfl-broadcasts, then 32 independent 128B
// row gathers (pure sum, no per-edge weight — factorized into dinv).
__device__ __forceinline__ float2 row_gather(const __half2* __restrict__ tin,
                                             int beg, int end, int lane) {
    float2 acc = make_float2(0.f, 0.f);
    const __half2* tlane = tin + lane;
    int j0 = beg;
    for (; j0 + 32 <= end; j0 += 32) {
        int s = __ldg(&g_src[j0 + lane]);
#pragma unroll
        for (int t = 0; t < 32; ++t) {
            int ss = __shfl_sync(0xFFFFFFFFu, s, t);
            float2 v = __half22float2(__ldg(&tlane[ss * 32]));
            acc.x += v.x; acc.y += v.y;
        }
    }
    int n = end - j0;
    if (n > 0) {
        int s = (lane < n) ? __ldg(&g_src[j0 + lane]) : 0;
#pragma unroll 8
        for (int t = 0; t < n; ++t) {
            int ss = __shfl_sync(0xFFFFFFFFu, s, t);
            float2 v = __half22float2(__ldg(&tlane[ss * 32]));
            acc.x += v.x; acc.y += v.y;
        }
    }
    return acc;
}

// hop d: Tx = -dinv * sum(u_{d-1}[src]) (fp32, unrounded -> hidden RMW);
//        u_d = dinv * Tx (fp16, next gather). d odd -> writes A, even -> B.
// R9-proven geometry: 256 thr, warp-per-row. hidden/dinv loads hoisted above
// the gather so their latency hides under it.
__global__ __launch_bounds__(256) void hop_kernel(int d) {
    int row = blockIdx.x * 8 + (threadIdx.x >> 5);
    if (row >= N_NODES) return;
    int lane = threadIdx.x & 31;

    const __half2* tin = (d == 1) ? (const __half2*)g_u0
                        : ((d & 1) ? (const __half2*)g_uB : (const __half2*)g_uA);
    __half2* tout = (d & 1) ? (__half2*)g_uA : (__half2*)g_uB;

    int beg = __ldg(&g_rowptr[row]);
    int end = __ldg(&g_rowptr[row + 1]);
    int idx = row * 32 + lane;
    float di = __ldg(&g_dinv[row]);
    float2 h = __ldcs(&((float2*)g_hidden)[idx]);

    float2 acc = row_gather(tin, beg, end, lane);
    float txx = -di * acc.x;
    float txy = -di * acc.y;
    tout[idx] = __floats2half2_rn(di * txx, di * txy);
    float c = g_coeff[d];
    h.x = fmaf(c, txx, h.x);
    h.y = fmaf(c, txy, h.y);
    __stcs(&((float2*)g_hidden)[idx], h);
}

// ---------------- last hop (d=10) fused with log_softmax epilogue ----------------
// d=9 odd -> its output is in g_uA.
__global__ __launch_bounds__(256) void hop_final_kernel(float* __restrict__ out) {
    int row = blockIdx.x * 8 + (threadIdx.x >> 5);
    if (row >= N_NODES) return;
    int lane = threadIdx.x & 31;

    int beg = __ldg(&g_rowptr[row]);
    int end = __ldg(&g_rowptr[row + 1]);
    int idx = row * 32 + lane;
    float di = __ldg(&g_dinv[row]);
    float2 h = __ldcs(&((const float2*)g_hidden)[idx]);
    float2 x = __ldcs(&((const float2*)g_xc)[idx]);

    float2 acc = row_gather((const __half2*)g_uA, beg, end, lane);

    float c = g_coeff[DORD];
    float vx = fmaf(c, -di * acc.x, h.x) + x.x;
    float vy = fmaf(c, -di * acc.y, h.y) + x.y;
    float m = fmaxf(vx, vy);
#pragma unroll
    for (int o = 16; o; o >>= 1) m = fmaxf(m, __shfl_xor_sync(0xFFFFFFFFu, m, o));
    float s = expf(vx - m) + expf(vy - m);
#pragma unroll
    for (int o = 16; o; o >>= 1) s += __shfl_xor_sync(0xFFFFFFFFu, s, o);
    float l = m + logf(s);
    __stcs(&((float2*)out)[idx], make_float2(vx - l, vy - l));
}

// ---------------- launch ----------------
extern "C" void kernel_launch(void* const* d_in, const int* in_sizes, int n_in,
                              void* d_out, int out_size) {
    const float* feature = (const float*)d_in[0];
    const int*   edges   = (const int*)d_in[1];   // int32
    const float* W1      = (const float*)d_in[2];
    const float* b1      = (const float*)d_in[3];
    const float* W2      = (const float*)d_in[4];
    const float* b2      = (const float*)d_in[5];
    const float* alpha   = (const float*)d_in[6];
    const float* beta    = (const float*)d_in[7];
    float* out           = (float*)d_out;

    const int TB = 256;
    int gN   = (N_NODES + TB - 1) / TB;
    int gE   = (E_EDGES + TB - 1) / TB;
    int gRow = (N_NODES + 7) / 8;            // 256-thr warp-per-row (R9-proven)
    int gG   = (N_NODES + 63) / 64;
    int nb   = (N_NODES + 1023) / 1024;

    init_kernel<<<gN, TB>>>(alpha, beta);
    pass1_kernel<<<gE, TB>>>(edges);
    scan1_kernel<<<nb, 1024>>>(N_NODES);     // + fused dinv
    scan2_kernel<<<1, 32>>>(nb);
    scan3_kernel<<<nb, 1024>>>(N_NODES);
    scatter_kernel<<<gE, TB>>>(edges);

    gemm1_kernel<<<gG, TB>>>(feature, W1, b1);
    gemm2_kernel<<<gG, TB>>>(W2, b2);

    for (int d = 1; d < DORD; ++d)
        hop_kernel<<<gRow, TB>>>(d);
    hop_final_kernel<<<gRow, TB>>>(out);
}

// round 17
// speedup vs baseline: 1.9091x; 1.1929x over previous
#include <cuda_runtime.h>
#include <cuda_fp16.h>
#include <cstdint>
#include <math.h>

#define N_NODES 100000
#define E_EDGES 3200000
#define F_IN    500
#define HID     64
#define CCH     64
#define KFREQ   5
#define DORD    10

// ---------------- scratch (static device globals; no allocation) ----------------
__device__ __align__(16) float  g_xh[N_NODES * HID];     // relu(feature@W1+b1)
__device__ __align__(16) float  g_xc[N_NODES * CCH];     // lin2 output fp32
__device__ __align__(16) __half g_u0[N_NODES * CCH];     // u0 = dinv*xc (fp16)
__device__ __align__(16) __half g_uA[N_NODES * CCH];     // fp16 scaled-state ping (odd d)
__device__ __align__(16) __half g_uB[N_NODES * CCH];     // fp16 scaled-state pong (even d)
__device__ __align__(16) float  g_hidden[N_NODES * CCH]; // fp32 accumulator (init c0*xc)
__device__ int    g_src[E_EDGES];                        // CSR-by-dst: src per edge
__device__ int    g_deg[N_NODES];
__device__ int    g_indeg[N_NODES];
__device__ float  g_dinv[N_NODES];
__device__ int    g_rowptr[N_NODES + 1];
__device__ int    g_cursor[N_NODES + 1];
__device__ int    g_tmp[N_NODES];
__device__ int    g_btot[128];
__device__ int    g_boff[128];
__device__ float  g_coeff[16];

// ---------------- init: zero counters + Taylor coeffs (fused) ----------------
__global__ void init_kernel(const float* __restrict__ alpha,
                            const float* __restrict__ beta) {
    int i = blockIdx.x * blockDim.x + threadIdx.x;
    if (i < N_NODES) { g_deg[i] = 0; g_indeg[i] = 0; }
    if (blockIdx.x == 0 && threadIdx.x <= DORD) {
        int d = threadIdx.x;
        float acc = 0.0f;
        for (int k = 0; k < KFREQ; ++k) {
            double x = (double)(k + 1) * 3.14159265358979323846;
            double p = 1.0;
            for (int j = 0; j < d; ++j) p *= x;
            double f = 1.0;
            for (int j = 2; j <= d; ++j) f *= (double)j;
            double sinc = 0.0, cosc = 0.0;
            if ((d & 1) == 0) {
                double sgn = (((d / 2) & 1) == 0) ? 1.0 : -1.0;
                cosc = sgn * p / f;
            } else {
                double sgn = ((((d - 1) / 2) & 1) == 0) ? 1.0 : -1.0;
                sinc = sgn * p / f;
            }
            acc += alpha[k] * (float)sinc + beta[k] * (float)cosc;
        }
        g_coeff[d] = acc;
    }
}

// edges buffer is int32 (jax x64 disabled)
__global__ void pass1_kernel(const int* __restrict__ edges) {
    int e = blockIdx.x * blockDim.x + threadIdx.x;
    if (e >= E_EDGES) return;
    int s = edges[e];
    int d = edges[E_EDGES + e];
    if (s != d && (unsigned)s < N_NODES && (unsigned)d < N_NODES) {
        atomicAdd(&g_deg[s], 1);
        atomicAdd(&g_indeg[d], 1);
    }
}

// ------- scan1 (block-local inclusive scan of indeg) + dinv fused -------
__global__ void scan1_kernel(int n) {
    __shared__ int s[1024];
    int i = blockIdx.x * 1024 + threadIdx.x;
    if (i < n) {
        int dg = g_deg[i];
        g_dinv[i] = (dg > 0) ? rsqrtf((float)dg) : 0.0f;
    }
    int v = (i < n) ? g_indeg[i] : 0;
    s[threadIdx.x] = v;
    __syncthreads();
    for (int off = 1; off < 1024; off <<= 1) {
        int t = (threadIdx.x >= off) ? s[threadIdx.x - off] : 0;
        __syncthreads();
        s[threadIdx.x] += t;
        __syncthreads();
    }
    if (i < n) g_tmp[i] = s[threadIdx.x];
    if (threadIdx.x == 1023) g_btot[blockIdx.x] = s[1023];
}

__global__ void scan2_kernel(int nb) {
    if (threadIdx.x == 0 && blockIdx.x == 0) {
        int run = 0;
        for (int b = 0; b < nb; ++b) { g_boff[b] = run; run += g_btot[b]; }
    }
}

__global__ void scan3_kernel(int n) {
    int i = blockIdx.x * 1024 + threadIdx.x;
    if (i < n) {
        int v = g_tmp[i] + g_boff[blockIdx.x];
        g_rowptr[i + 1] = v;
        if (i + 1 < N_NODES) g_cursor[i + 1] = v;
        if (i == 0) { g_rowptr[0] = 0; g_cursor[0] = 0; }
    }
}

__global__ void scatter_kernel(const int* __restrict__ edges) {
    int e = blockIdx.x * blockDim.x + threadIdx.x;
    if (e >= E_EDGES) return;
    int s = edges[e];
    int d = edges[E_EDGES + e];
    if (s != d && (unsigned)s < N_NODES && (unsigned)d < N_NODES) {
        int pos = atomicAdd(&g_cursor[d], 1);
        g_src[pos] = s;
    }
}

// ---------------- packed f32x2 FMA helper (GEMM2) ----------------
__device__ __forceinline__ void ffma2(unsigned long long& acc,
                                      unsigned long long a,
                                      unsigned long long b) {
    asm("fma.rn.f32x2 %0, %1, %2, %0;" : "+l"(acc) : "l"(a), "l"(b));
}
__device__ __forceinline__ float2 unpack2(unsigned long long p) {
    float2 r;
    asm("mov.b64 {%0, %1}, %2;" : "=f"(r.x), "=f"(r.y) : "l"(p));
    return r;
}

__device__ __forceinline__ uint32_t to_tf32(float f) {
    uint32_t r;
    asm("cvt.rna.tf32.f32 %0, %1;" : "=r"(r) : "f"(f));
    return r;
}

// ---------------- GEMM1: xh = relu(feature @ W1 + b1) via tf32 mma.sync ----------------
// Block 128x64, K-chunks of 32, 8 warps; warp = 16 rows x 64 cols (8 n-tiles).
// A smem row-major pitch 36 (36i mod 32 = 4i: ldmatrix rows hit distinct bank
// groups). B smem n-major pitch 36 so ldmatrix.x2 yields {b0,b1} directly.
#define G1_PITCH 36
__global__ __launch_bounds__(256) void gemm1_mma_kernel(const float* __restrict__ feat,
                                                        const float* __restrict__ W1,
                                                        const float* __restrict__ b1v) {
    __shared__ __align__(16) uint32_t As[128 * G1_PITCH];
    __shared__ __align__(16) uint32_t Bs[64 * G1_PITCH];
    int tid = threadIdx.x;
    int warp = tid >> 5, lane = tid & 31;
    int row0 = blockIdx.x * 128;

    float c[8][4];
#pragma unroll
    for (int i = 0; i < 8; ++i)
#pragma unroll
        for (int j = 0; j < 4; ++j) c[i][j] = 0.f;

    uint32_t a_base = (uint32_t)__cvta_generic_to_shared(As);
    uint32_t b_base = (uint32_t)__cvta_generic_to_shared(Bs);
    // A ldmatrix quadrants: threads 0-7 rows 0-7 / 8-15 rows 8-15 (cols 0-3),
    // 16-23 rows 0-7 / 24-31 rows 8-15 (cols 4-7).
    uint32_t a_addr = a_base + (((warp * 16 + (lane & 15)) * G1_PITCH + (lane >> 4) * 4) << 2);
    int l15 = lane & 15;

    for (int k0 = 0; k0 < 512; k0 += 32) {           // 16 chunks (500 padded to 512)
        // ---- load A chunk: 128x32, 4 float4/thread ----
#pragma unroll
        for (int i = 0; i < 4; ++i) {
            int L = tid + 256 * i;
            int r = L >> 3;
            int f4 = L & 7;
            int k = k0 + f4 * 4;
            float4 v = make_float4(0.f, 0.f, 0.f, 0.f);
            if (row0 + r < N_NODES && k < F_IN)
                v = *(const float4*)&feat[(row0 + r) * F_IN + k];
            uint4 t;
            t.x = to_tf32(v.x); t.y = to_tf32(v.y);
            t.z = to_tf32(v.z); t.w = to_tf32(v.w);
            *(uint4*)&As[r * G1_PITCH + f4 * 4] = t;
        }
        // ---- load B chunk: 32x64, transposed to n-major ----
#pragma unroll
        for (int i = 0; i < 2; ++i) {
            int L = tid + 256 * i;
            int k = L >> 4;            // 0..31
            int f4 = L & 15;           // 0..15 -> n = f4*4
            float4 v = make_float4(0.f, 0.f, 0.f, 0.f);
            if (k0 + k < F_IN)
                v = *(const float4*)&W1[(k0 + k) * HID + f4 * 4];
            int n = f4 * 4;
            Bs[(n + 0) * G1_PITCH + k] = to_tf32(v.x);
            Bs[(n + 1) * G1_PITCH + k] = to_tf32(v.y);
            Bs[(n + 2) * G1_PITCH + k] = to_tf32(v.z);
            Bs[(n + 3) * G1_PITCH + k] = to_tf32(v.w);
        }
        __syncthreads();

        // ---- A fragments for 4 k-steps ----
        uint32_t a[4][4];
#pragma unroll
        for (int s = 0; s < 4; ++s) {
            uint32_t addr = a_addr + ((s * 8) << 2);
            asm volatile("ldmatrix.sync.aligned.m8n8.x4.b16 {%0,%1,%2,%3}, [%4];"
                         : "=r"(a[s][0]), "=r"(a[s][1]), "=r"(a[s][2]), "=r"(a[s][3])
                         : "r"(addr));
        }
        // ---- 8 n-tiles x 4 k-steps ----
#pragma unroll
        for (int nt = 0; nt < 8; ++nt) {
#pragma unroll
            for (int s = 0; s < 4; ++s) {
                uint32_t baddr = b_base +
                    (((nt * 8 + (l15 & 7)) * G1_PITCH + s * 8 + ((l15 >> 3) & 1) * 4) << 2);
                uint32_t b0, b1;
                asm volatile("ldmatrix.sync.aligned.m8n8.x2.b16 {%0,%1}, [%2];"
                             : "=r"(b0), "=r"(b1) : "r"(baddr));
                asm volatile("mma.sync.aligned.m16n8k8.row.col.f32.tf32.tf32.f32 "
                             "{%0,%1,%2,%3}, {%4,%5,%6,%7}, {%8,%9}, {%0,%1,%2,%3};"
                             : "+f"(c[nt][0]), "+f"(c[nt][1]), "+f"(c[nt][2]), "+f"(c[nt][3])
                             : "r"(a[s][0]), "r"(a[s][1]), "r"(a[s][2]), "r"(a[s][3]),
                               "r"(b0), "r"(b1));
            }
        }
        __syncthreads();
    }

    // ---- epilogue: bias + relu ----
    int mrow = row0 + warp * 16 + (lane >> 2);
    int colb = (lane & 3) * 2;
#pragma unroll
    for (int nt = 0; nt < 8; ++nt) {
        int col = nt * 8 + colb;
        float bv0 = __ldg(&b1v[col]);
        float bv1 = __ldg(&b1v[col + 1]);
        if (mrow < N_NODES) {
            float2 o = make_float2(fmaxf(c[nt][0] + bv0, 0.f),
                                   fmaxf(c[nt][1] + bv1, 0.f));
            *(float2*)&g_xh[mrow * HID + col] = o;
        }
        if (mrow + 8 < N_NODES) {
            float2 o = make_float2(fmaxf(c[nt][2] + bv0, 0.f),
                                   fmaxf(c[nt][3] + bv1, 0.f));
            *(float2*)&g_xh[(mrow + 8) * HID + col] = o;
        }
    }
}

// ---------------- GEMM2: xc = xh @ W2 + b2 ; hidden = c0*xc ; u0 = dinv*xc ----------------
__global__ __launch_bounds__(256) void gemm2_kernel(const float* __restrict__ W2,
                                                    const float* __restrict__ b2) {
    __shared__ __align__(16) float2 As2[16 * 65];
    __shared__ __align__(16) float  Ws[16 * 64];
    int tid = threadIdx.x;
    int tx = tid & 15, ty = tid >> 4;
    int row0 = blockIdx.x * 64;
    int kkA = tid & 15;
    int rA = (tid >> 4) * 4;
    unsigned long long acc[4][2] = {};

    for (int k0 = 0; k0 < HID; k0 += 16) {
#pragma unroll
        for (int i = 0; i < 4; ++i) {
            int r = row0 + rA + i;
            float v = 0.0f;
            if (r < N_NODES) v = g_xh[r * HID + k0 + kkA];
            As2[kkA * 65 + rA + i] = make_float2(v, v);
        }
        {
            int L = tid * 4;
            int kk = L >> 6;
            int n = L & 63;
            float4 w4 = *(const float4*)&W2[(k0 + kk) * CCH + n];
            *(float4*)&Ws[kk * 64 + n] = w4;
        }
        __syncthreads();
#pragma unroll
        for (int kk = 0; kk < 16; ++kk) {
            ulonglong2 bp = *(const ulonglong2*)&Ws[kk * 64 + tx * 4];
            const unsigned long long* ap =
                (const unsigned long long*)&As2[kk * 65 + ty * 4];
#pragma unroll
            for (int i = 0; i < 4; ++i) {
                unsigned long long a = ap[i];
                ffma2(acc[i][0], a, bp.x);
                ffma2(acc[i][1], a, bp.y);
            }
        }
        __syncthreads();
    }
    float c0 = g_coeff[0];
#pragma unroll
    for (int i = 0; i < 4; ++i) {
        int r = row0 + ty * 4 + i;
        if (r >= N_NODES) continue;
        float2 p0 = unpack2(acc[i][0]);
        float2 p1 = unpack2(acc[i][1]);
        int c = tx * 4;
        float v0 = p0.x + __ldg(&b2[c + 0]);
        float v1 = p0.y + __ldg(&b2[c + 1]);
        float v2 = p1.x + __ldg(&b2[c + 2]);
        float v3 = p1.y + __ldg(&b2[c + 3]);
        float* xr = &g_xc[r * CCH + c];
        xr[0] = v0; xr[1] = v1; xr[2] = v2; xr[3] = v3;
        float* hr = &g_hidden[r * CCH + c];
        hr[0] = c0 * v0; hr[1] = c0 * v1; hr[2] = c0 * v2; hr[3] = c0 * v3;
        float di = __ldg(&g_dinv[r]);       // u0 = dinv * xc
        __half2* u0 = (__half2*)&g_u0[r * CCH + c];
        u0[0] = __floats2half2_rn(di * v0, di * v1);
        u0[1] = __floats2half2_rn(di * v2, di * v3);
    }
}

// ---------------- hop gather: sum of u over the row's sources ----------------
__device__ __forceinline__ float2 row_gather(const __half2* __restrict__ tin,
                                             int beg, int end, int lane) {
    float2 acc = make_float2(0.f, 0.f);
    const __half2* tlane = tin + lane;
    int j0 = beg;
    for (; j0 + 32 <= end; j0 += 32) {
        int s = __ldg(&g_src[j0 + lane]);
#pragma unroll
        for (int t = 0; t < 32; ++t) {
            int ss = __shfl_sync(0xFFFFFFFFu, s, t);
            float2 v = __half22float2(__ldg(&tlane[ss * 32]));
            acc.x += v.x; acc.y += v.y;
        }
    }
    int n = end - j0;
    if (n > 0) {
        int s = (lane < n) ? __ldg(&g_src[j0 + lane]) : 0;
#pragma unroll 8
        for (int t = 0; t < n; ++t) {
            int ss = __shfl_sync(0xFFFFFFFFu, s, t);
            float2 v = __half22float2(__ldg(&tlane[ss * 32]));
            acc.x += v.x; acc.y += v.y;
        }
    }
    return acc;
}

// hop d: Tx = -dinv * sum(u_{d-1}[src]) (fp32 -> hidden RMW);
//        u_d = dinv * Tx (fp16). d odd -> writes A, even -> B.
__global__ __launch_bounds__(256) void hop_kernel(int d) {
    int row = blockIdx.x * 8 + (threadIdx.x >> 5);
    if (row >= N_NODES) return;
    int lane = threadIdx.x & 31;

    const __half2* tin = (d == 1) ? (const __half2*)g_u0
                        : ((d & 1) ? (const __half2*)g_uB : (const __half2*)g_uA);
    __half2* tout = (d & 1) ? (__half2*)g_uA : (__half2*)g_uB;

    int beg = __ldg(&g_rowptr[row]);
    int end = __ldg(&g_rowptr[row + 1]);
    int idx = row * 32 + lane;
    float di = __ldg(&g_dinv[row]);
    float2 h = __ldcs(&((float2*)g_hidden)[idx]);

    float2 acc = row_gather(tin, beg, end, lane);
    float txx = -di * acc.x;
    float txy = -di * acc.y;
    tout[idx] = __floats2half2_rn(di * txx, di * txy);
    float c = g_coeff[d];
    h.x = fmaf(c, txx, h.x);
    h.y = fmaf(c, txy, h.y);
    __stcs(&((float2*)g_hidden)[idx], h);
}

// ---------------- last hop (d=10) fused with log_softmax epilogue ----------------
__global__ __launch_bounds__(256) void hop_final_kernel(float* __restrict__ out) {
    int row = blockIdx.x * 8 + (threadIdx.x >> 5);
    if (row >= N_NODES) return;
    int lane = threadIdx.x & 31;

    int beg = __ldg(&g_rowptr[row]);
    int end = __ldg(&g_rowptr[row + 1]);
    int idx = row * 32 + lane;
    float di = __ldg(&g_dinv[row]);
    float2 h = __ldcs(&((const float2*)g_hidden)[idx]);
    float2 x = __ldcs(&((const float2*)g_xc)[idx]);

    float2 acc = row_gather((const __half2*)g_uA, beg, end, lane);

    float c = g_coeff[DORD];
    float vx = fmaf(c, -di * acc.x, h.x) + x.x;
    float vy = fmaf(c, -di * acc.y, h.y) + x.y;
    float m = fmaxf(vx, vy);
#pragma unroll
    for (int o = 16; o; o >>= 1) m = fmaxf(m, __shfl_xor_sync(0xFFFFFFFFu, m, o));
    float s = expf(vx - m) + expf(vy - m);
#pragma unroll
    for (int o = 16; o; o >>= 1) s += __shfl_xor_sync(0xFFFFFFFFu, s, o);
    float l = m + logf(s);
    __stcs(&((float2*)out)[idx], make_float2(vx - l, vy - l));
}

// ---------------- launch ----------------
extern "C" void kernel_launch(void* const* d_in, const int* in_sizes, int n_in,
                              void* d_out, int out_size) {
    const float* feature = (const float*)d_in[0];
    const int*   edges   = (const int*)d_in[1];   // int32
    const float* W1      = (const float*)d_in[2];
    const float* b1      = (const float*)d_in[3];
    const float* W2      = (const float*)d_in[4];
    const float* b2      = (const float*)d_in[5];
    const float* alpha   = (const float*)d_in[6];
    const float* beta    = (const float*)d_in[7];
    float* out           = (float*)d_out;

    const int TB = 256;
    int gN   = (N_NODES + TB - 1) / TB;
    int gE   = (E_EDGES + TB - 1) / TB;
    int gRow = (N_NODES + 7) / 8;
    int gG1  = (N_NODES + 127) / 128;        // 782 (mma gemm1)
    int gG2  = (N_NODES + 63) / 64;
    int nb   = (N_NODES + 1023) / 1024;

    init_kernel<<<gN, TB>>>(alpha, beta);
    pass1_kernel<<<gE, TB>>>(edges);
    scan1_kernel<<<nb, 1024>>>(N_NODES);
    scan2_kernel<<<1, 32>>>(nb);
    scan3_kernel<<<nb, 1024>>>(N_NODES);
    scatter_kernel<<<gE, TB>>>(edges);

    gemm1_mma_kernel<<<gG1, TB>>>(feature, W1, b1);
    gemm2_kernel<<<gG2, TB>>>(W2, b2);

    for (int d = 1; d < DORD; ++d)
        hop_kernel<<<gRow, TB>>>(d);
    hop_final_kernel<<<gRow, TB>>>(out);
}